// round 4
// baseline (speedup 1.0000x reference)
#include <cuda_runtime.h>

// CrossAttention_47502338294587 — algebraic collapse:
// K/V come from one per-batch visual token broadcast over T -> logit rows are
// constant -> softmax exactly uniform -> y == v.
// output[b,t,:] = ((vf @ Wv + bv) @ Wp + bp)[b,:]   (independent of x,Wq,Wk).
//
// 5 launches (graph-captured, launch boundary = sync, no atomics):
//  gemm_split(vf,Wv) -> part1      [1024 blocks, ONE LDG.128 of W per thread]
//  fold(part1,+bv)   -> g_vv
//  gemm_split(vv,Wp) -> part2
//  fold(part2,+bp)   -> g_row
//  bcast(g_row)      -> out        [write-bound, full-line STG.128]

static constexpr int C = 1024;
static constexpr int B = 4;
static constexpr int T = 1024;
static constexpr int KS = 32;          // k-splits -> 32 k-rows per block
static constexpr int CG = 32;          // 32 float columns (one 128B line) per block

__device__ float g_part1[KS * B * C];  // 512 KB, L2-resident
__device__ float g_part2[KS * B * C];
__device__ float g_vv[B * C];
__device__ float g_row[B * C];

// Block (cg, ks): cols [cg*32, cg*32+32), k in [ks*32, ks*32+32).
// Thread t: f4 = t&7 (float4 col), kr = t>>3 (k-row). Exactly one LDG.128 of W
// per thread -> the entire 4 MB W is in flight chip-wide immediately.
__global__ void __launch_bounds__(256) gemm_split(
    const float* __restrict__ in,      // [B][C]
    const float* __restrict__ W,       // [C][C] row-major
    float* __restrict__ part)          // [KS][B][C]
{
    __shared__ float  s_in[B][KS];     // 512 B
    __shared__ float4 s_red[256][B];   // 16 KB

    const int cg = blockIdx.x;         // 0..31
    const int ks = blockIdx.y;         // 0..31
    const int t  = threadIdx.x;
    const int f4 = t & 7;
    const int kr = t >> 3;             // 0..31
    const int k0 = ks * KS;

    // Issue the W load first (independent of staging)
    const float4 w = ((const float4*)W)[(size_t)(k0 + kr) * (C / 4) + cg * 8 + f4];

    if (t < B * KS) {                  // 128 threads stage the input k-tile
        const int b  = t >> 5;
        const int kk = t & 31;
        s_in[b][kk] = in[b * C + k0 + kk];
    }
    __syncthreads();

    #pragma unroll
    for (int b = 0; b < B; b++) {
        const float s = s_in[b][kr];
        float4 a;
        a.x = s * w.x; a.y = s * w.y; a.z = s * w.z; a.w = s * w.w;
        s_red[t][b] = a;
    }
    __syncthreads();

    // tree-reduce over kr (threads sharing f4 are t = f4 + 8*kr)
    #pragma unroll
    for (int off = 16; off > 0; off >>= 1) {
        if (kr < off) {
            #pragma unroll
            for (int b = 0; b < B; b++) {
                float4 a = s_red[t][b];
                const float4 o = s_red[t + off * 8][b];
                a.x += o.x; a.y += o.y; a.z += o.z; a.w += o.w;
                s_red[t][b] = a;
            }
        }
        __syncthreads();
    }

    if (t < 8) {
        #pragma unroll
        for (int b = 0; b < B; b++)
            ((float4*)part)[(ks * B + b) * (C / 4) + cg * 8 + t] = s_red[t][b];
    }
}

// outv[b][c] = bias[c] + sum_s part[s][b][c].  4096 threads, 32 independent
// L2-resident loads each (MLP=32) -> latency-covered, fixed summation order.
__global__ void __launch_bounds__(256) fold_kernel(
    const float* __restrict__ part,
    const float* __restrict__ bias,
    float* __restrict__ outv)
{
    const int i = blockIdx.x * 256 + threadIdx.x;  // 0..B*C-1
    const int c = i & (C - 1);
    float v = bias[c];
    #pragma unroll
    for (int s = 0; s < KS; s++)
        v += part[s * (B * C) + i];
    outv[i] = v;
}

// grid = B*(T/8) = 512 blocks; block = (b, 8 consecutive t-rows).
// Row value stays in registers; 8 coalesced full-line STG.128 per thread.
__global__ void __launch_bounds__(256) bcast_kernel(
    const float* __restrict__ row, float* __restrict__ out)
{
    const int b   = blockIdx.x >> 7;
    const int tch = blockIdx.x & 127;
    const int t   = threadIdx.x;       // float4 column 0..255

    const float4 r = ((const float4*)row)[b * (C / 4) + t];
    float4* o4 = (float4*)out + ((size_t)b * T + tch * 8) * (C / 4);
    #pragma unroll
    for (int tt = 0; tt < 8; tt++)
        o4[tt * (C / 4) + t] = r;
}

extern "C" void kernel_launch(void* const* d_in, const int* in_sizes, int n_in,
                              void* d_out, int out_size)
{
    (void)in_sizes; (void)n_in; (void)out_size;
    const float* vf = (const float*)d_in[1];  // visual_features [B,C]
    const float* Wv = (const float*)d_in[6];
    const float* bv = (const float*)d_in[7];
    const float* Wp = (const float*)d_in[8];
    const float* bp = (const float*)d_in[9];
    float* out = (float*)d_out;

    float *p1, *p2, *pvv, *prow;
    cudaGetSymbolAddress((void**)&p1,  g_part1);
    cudaGetSymbolAddress((void**)&p2,  g_part2);
    cudaGetSymbolAddress((void**)&pvv, g_vv);
    cudaGetSymbolAddress((void**)&prow, g_row);

    const dim3 g(C / CG, KS);                       // 32 x 32 = 1024 blocks
    gemm_split<<<g, 256>>>(vf, Wv, p1);
    fold_kernel<<<B * C / 256, 256>>>(p1, bv, pvv); // 16 blocks
    gemm_split<<<g, 256>>>(pvv, Wp, p2);
    fold_kernel<<<B * C / 256, 256>>>(p2, bp, prow);
    bcast_kernel<<<B * (T / 8), 256>>>(prow, out);  // 512 blocks
}

// round 7
// speedup vs baseline: 2.1164x; 2.1164x over previous
#include <cuda_runtime.h>

// CrossAttention_47502338294587 — algebraic collapse:
// K/V come from one per-batch visual token broadcast over T -> every logit row
// is constant -> softmax exactly uniform -> y == v.
// out[b,t,:] = ((vf @ Wv + bv) @ Wp + bp)[b,:]   (independent of x, Wq, Wk).
//
// ONE persistent kernel (measured: ~5us per-launch overhead dominated the
// multi-kernel versions). GRID=256 so wave-1 co-residency needs only
// occupancy 2/SM (smem 21KB, regs<=64) — deadlock-proof spin barrier.
//   Phase A : 256 CTAs (32 cg x 8 ks) -> partials of vf@Wv into g_part1 (L2)
//   Barrier : epoch grid barrier
//   Phase B : CTA (b,cg,th) folds vv[b,:] = bv + sum(part1), computes
//             row[b, 32-col slice] = vv @ Wp[:,slice] + bp  (fixed order)
//   Phase C : same CTA broadcasts its slice over its 512 t-rows (STG.128).

static constexpr int C    = 1024;
static constexpr int B    = 4;
static constexpr int T    = 1024;
static constexpr int KS   = 8;       // phase-A k-splits (128 k-rows each)
static constexpr int GRID = 256;

__device__ float    g_part1[KS * B * C];   // 128 KB scratch (L2-resident)
__device__ unsigned g_cnt   = 0;           // barrier arrivals (self-resetting)
__device__ unsigned g_epoch = 0;           // barrier releases (monotonic)

__global__ void __launch_bounds__(256, 4) fused_kernel(
    const float* __restrict__ vf,   // [B][C]
    const float* __restrict__ Wv,   // [C][C]
    const float* __restrict__ bv,   // [C]
    const float* __restrict__ Wp,   // [C][C]
    const float* __restrict__ bp,   // [C]
    float* __restrict__ out)        // [B][T][C]
{
    __shared__ float  s_in[B][128];    // 2 KB
    __shared__ float4 s_red[256][B];   // 16 KB
    __shared__ float  s_vv[C];         // 4 KB
    __shared__ float4 s_row[8];

    const int t  = threadIdx.x;
    const int f4 = t & 7;              // float4 column within 32-col group
    const int kr = t >> 3;             // 0..31

    // Epoch read before any CTA can possibly release this launch's barrier
    // (release requires ALL arrivals, so this read is race-free).
    const unsigned e0 = *(volatile unsigned*)&g_epoch;

    // ================= Phase A: partials of vf @ Wv =================
    {
        const int cg = blockIdx.x & 31;
        const int ks = blockIdx.x >> 5;      // 0..7
        const int k0 = ks * 128;

        const float4* W4 = (const float4*)Wv;
        float4 w[4];
        #pragma unroll
        for (int i = 0; i < 4; i++)          // 4 independent full-line LDG.128
            w[i] = W4[(size_t)(k0 + kr + 32 * i) * 256 + cg * 8 + f4];

        #pragma unroll
        for (int i = 0; i < 2; i++) {        // stage vf k-tile (512 values)
            const int idx = t + 256 * i;
            s_in[idx >> 7][idx & 127] = vf[(idx >> 7) * C + k0 + (idx & 127)];
        }
        __syncthreads();

        #pragma unroll
        for (int b = 0; b < B; b++) {
            float4 a = make_float4(0.f, 0.f, 0.f, 0.f);
            #pragma unroll
            for (int i = 0; i < 4; i++) {
                const float s = s_in[b][kr + 32 * i];
                a.x = fmaf(s, w[i].x, a.x);
                a.y = fmaf(s, w[i].y, a.y);
                a.z = fmaf(s, w[i].z, a.z);
                a.w = fmaf(s, w[i].w, a.w);
            }
            s_red[t][b] = a;
        }
        __syncthreads();

        #pragma unroll
        for (int off = 16; off > 0; off >>= 1) {   // reduce over kr
            if (kr < off) {
                #pragma unroll
                for (int b = 0; b < B; b++) {
                    float4 a = s_red[t][b];
                    const float4 o = s_red[t + off * 8][b];
                    a.x += o.x; a.y += o.y; a.z += o.z; a.w += o.w;
                    s_red[t][b] = a;
                }
            }
            __syncthreads();
        }

        if (t < 8) {
            #pragma unroll
            for (int b = 0; b < B; b++)
                ((float4*)g_part1)[(ks * B + b) * 256 + cg * 8 + t] = s_red[t][b];
            __threadfence();               // publish before arriving
        }
        __syncthreads();
    }

    // ================= Grid barrier (epoch-based) =================
    if (t == 0) {
        const unsigned old = atomicAdd(&g_cnt, 1);
        if (old == GRID - 1) {
            g_cnt = 0;                      // reset for next graph replay
            __threadfence();
            atomicAdd(&g_epoch, 1);         // release
        } else {
            while (*(volatile unsigned*)&g_epoch == e0) __nanosleep(32);
        }
        __threadfence();
    }
    __syncthreads();

    // ============ Phase B: row[b, 32-col slice] = vv @ Wp + bp ============
    const int b  = blockIdx.x >> 6;          // 0..3
    const int cg = (blockIdx.x >> 1) & 31;   // 0..31
    const int th = blockIdx.x & 1;           // t-half 0..1

    {   // fold vv[b][:] into smem (L2 reads -> no L1 staleness)
        #pragma unroll
        for (int i = 0; i < 4; i++) {
            const int c = t + 256 * i;
            float v = bv[c];
            #pragma unroll
            for (int ks = 0; ks < KS; ks++)
                v += __ldcg(&g_part1[(ks * B + b) * C + c]);
            s_vv[c] = v;
        }
    }
    __syncthreads();

    {
        const float4* W4 = (const float4*)Wp;
        float4 acc = make_float4(0.f, 0.f, 0.f, 0.f);
        #pragma unroll 8
        for (int i = 0; i < 32; i++) {       // k = kr + 32*i
            const int k = kr + 32 * i;
            const float4 w = W4[(size_t)k * 256 + cg * 8 + f4];
            const float s = s_vv[k];
            acc.x = fmaf(s, w.x, acc.x);
            acc.y = fmaf(s, w.y, acc.y);
            acc.z = fmaf(s, w.z, acc.z);
            acc.w = fmaf(s, w.w, acc.w);
        }
        s_red[t][0] = acc;
        __syncthreads();

        #pragma unroll
        for (int off = 16; off > 0; off >>= 1) {
            if (kr < off) {
                float4 a = s_red[t][0];
                const float4 o = s_red[t + off * 8][0];
                a.x += o.x; a.y += o.y; a.z += o.z; a.w += o.w;
                s_red[t][0] = a;
            }
            __syncthreads();
        }

        if (t < 8) {
            float4 r = s_red[t][0];
            const float4 bpv = ((const float4*)bp)[cg * 8 + t];
            r.x += bpv.x; r.y += bpv.y; r.z += bpv.z; r.w += bpv.w;
            s_row[t] = r;
        }
        __syncthreads();
    }

    // ============ Phase C: broadcast slice over 512 t-rows ============
    {
        const float4 r = s_row[f4];
        float4* o4 = (float4*)out;
        const size_t base = ((size_t)b * T + th * 512) * 256 + cg * 8 + f4;
        #pragma unroll
        for (int i = 0; i < 16; i++)         // rows kr, kr+32, ..., kr+480
            o4[base + (size_t)(kr + 32 * i) * 256] = r;
    }
}

extern "C" void kernel_launch(void* const* d_in, const int* in_sizes, int n_in,
                              void* d_out, int out_size)
{
    (void)in_sizes; (void)n_in; (void)out_size;
    const float* vf = (const float*)d_in[1];  // visual_features [B,C]
    const float* Wv = (const float*)d_in[6];
    const float* bv = (const float*)d_in[7];
    const float* Wp = (const float*)d_in[8];
    const float* bp = (const float*)d_in[9];
    float* out = (float*)d_out;

    fused_kernel<<<GRID, 256>>>(vf, Wv, bv, Wp, bp, out);
}